// round 14
// baseline (speedup 1.0000x reference)
#include <cuda_runtime.h>
#include <math.h>
#include <stdint.h>

#define NN 10000
#define KK 16
#define EE (NN*KK)
#define HH 100
#define NB 10
#define NBP 16

// ---------------- scratch ----------------
__device__ float g_basis[EE*NBP];
__device__ float g_u[EE*3];
__device__ float g_h2A[3*EE*HH];
__device__ float g_f0a[NN*32];
__device__ float g_f0b[NN*32];
__device__ float g_f1a[NN*24];
__device__ float g_f1b[NN*24];
__device__ float g_w1tA[3*NBP*HH];
__device__ float g_w2tA[3*HH*HH];
__device__ float g_w3rA[3*83200];

struct Bias3 { const float* b[3]; };

// ---------------- helpers ----------------
__device__ __forceinline__ float f2tf32f(float v) {
    uint32_t r;
    asm("cvt.rna.tf32.f32 %0, %1;" : "=r"(r) : "f"(v));
    return __uint_as_float(r);
}

__device__ __forceinline__ void mma_tf32(float* c, const uint32_t* a, const uint32_t* b) {
    asm volatile("mma.sync.aligned.m16n8k8.row.col.f32.tf32.tf32.f32 "
        "{%0,%1,%2,%3}, {%4,%5,%6,%7}, {%8,%9}, {%0,%1,%2,%3};"
        : "+f"(c[0]), "+f"(c[1]), "+f"(c[2]), "+f"(c[3])
        : "r"(a[0]), "r"(a[1]), "r"(a[2]), "r"(a[3]), "r"(b[0]), "r"(b[1]));
}

__device__ __forceinline__ void cp16(void* dst_smem, const void* src, int bytes) {
    uint32_t d = (uint32_t)__cvta_generic_to_shared(dst_smem);
    asm volatile("cp.async.cg.shared.global [%0], [%1], 16, %2;"
                 :: "r"(d), "l"(src), "r"(bytes));
}

// ---------------- prep ----------------
__global__ void prep_kernel(const float* __restrict__ radii) {
    int e = blockIdx.x*blockDim.x + threadIdx.x;
    if (e >= EE) return;
    float x = radii[e*3+0], y = radii[e*3+1], z = radii[e*3+2];
    float r = sqrtf(x*x + y*y + z*z);
    float inv = 1.0f / (r + 1e-8f);
    g_u[e*3+0] = x*inv; g_u[e*3+1] = y*inv; g_u[e*3+2] = z*inv;
    float rs = r * 1.8f;
    #pragma unroll
    for (int b = 0; b < NBP; b++) {
        float v = 0.f;
        if (b < NB) {
            float d = rs - (float)b;
            if (fabsf(d) < 1.0f) {
                float c = cospif(0.5f * d);
                v = f2tf32f(c * c);
            }
        }
        g_basis[e*NBP + b] = v;
    }
}

// ---------------- fused weight prep ----------------
__global__ void prep_weights(
    const float* __restrict__ w1a, const float* __restrict__ w2a, const float* __restrict__ w3a,
    const float* __restrict__ w1b, const float* __restrict__ w2b, const float* __restrict__ w3b,
    const float* __restrict__ w1c, const float* __restrict__ w2c, const float* __restrict__ w3c) {
    int i = blockIdx.x*blockDim.x + threadIdx.x;
    if (i < 4800) {
        int l = i / 1600, r = i - l*1600;
        int row = r / HH;
        const float* s = (l==0) ? w1a : (l==1) ? w1b : w1c;
        g_w1tA[i] = (row < NB) ? f2tf32f(s[r]) : 0.f;
    } else if (i < 34800) {
        int j = i - 4800;
        int l = j / 10000, r = j - l*10000;
        const float* s = (l==0) ? w2a : (l==1) ? w2b : w2c;
        g_w2tA[j] = f2tf32f(s[r]);
    } else {
        int j = i - 34800;
        if (j < 3200) {
            g_w3rA[j] = w3a[j];
        } else if (j < 3200 + 83200) {
            int r = j - 3200;
            int k = r / 832, d = r - k*832;
            int src;
            if      (d < 384) { int o=d%24,      i2=d/24;       src = o*16 + i2; }
            else if (d < 576) { int t=d-384; int o=t%24, i2=t/24; src = 384 + o*8 + i2; }
            else if (d < 704) { int t=d-576; int o=t%8,  i2=t/8;  src = 576 + o*16 + i2; }
            else if (d < 768) { int t=d-704; int o=t%8,  i2=t/8;  src = 704 + o*8 + i2; }
            else              { int t=d-768; int o=t%8,  i2=t/8;  src = 768 + o*8 + i2; }
            g_w3rA[83200 + r] = w3b[k*832 + src];
        } else if (j < 3200 + 83200 + 76800) {
            int r = j - 3200 - 83200;
            int k = r / 768, d = r - k*768;
            int src;
            if (d < 512) { int o=d%32, i2=d/32; src = o*16 + i2; }
            else         { int t=d-512; int o=t%32, i2=t/32; src = 512 + o*8 + i2; }
            g_w3rA[2*83200 + r] = w3c[k*768 + src];
        }
    }
}

// ---------------- fused radial MLP (R12 geometry + Bs2 overlap) ----------------
// CTA = 256 edges, 512 threads = 16 warps (4m x 4n), warp tile 64x32.
#define FAS_S 20
#define FB1_S 136
#define FHS_S 104
#define FB2_S 136
#define FM_SMEM_FLOATS (256*FAS_S + 16*FB1_S + 256*FHS_S + 104*FB2_S)

__global__ void __launch_bounds__(512, 1)
fused_mlp(const float* __restrict__ basis,
          const float* __restrict__ w1A, const float* __restrict__ w2A,
          Bias3 b1, Bias3 b2,
          float* __restrict__ h2A) {
    extern __shared__ float smem[];
    float* As  = smem;                  // 256 x 20
    float* Bs1 = As + 256*FAS_S;        // 16 x 136
    float* Hs  = Bs1 + 16*FB1_S;        // 256 x 104
    float* Bs2 = Hs + 256*FHS_S;        // 104 x 136

    const int z = blockIdx.z;
    const float* w1 = w1A + z*NBP*HH;
    const float* w2 = w2A + z*HH*HH;
    const float* bias1 = b1.b[z];
    const float* bias2 = b2.b[z];
    float* C = h2A + (size_t)z*EE*HH;

    const int tid = threadIdx.x;
    const int lane = tid & 31, wid = tid >> 5;
    const int wm = (wid & 3) * 64;
    const int wn = (wid >> 2) * 32;
    const int m0 = blockIdx.y * 256;
    const int gr = lane >> 2, tg = lane & 3;

    // group 0: As + Bs1
    #pragma unroll
    for (int j = 0; j < 2; j++) {                       // As: 256x16
        int c = tid + j*512;
        int row = c >> 2, kch = (c & 3) * 4;
        cp16(As + row*FAS_S + kch, basis + (size_t)(m0+row)*NBP + kch, 16);
    }
    {                                                    // Bs1: 16x128 (pad n>=100)
        int k = tid >> 5, nch = (tid & 31) * 4;
        int bytes = (HH - nch) * 4;
        bytes = bytes < 0 ? 0 : (bytes > 16 ? 16 : bytes);
        const float* src = bytes ? (w1 + k*HH + nch) : w1;
        cp16(Bs1 + k*FB1_S + nch, src, bytes);
    }
    asm volatile("cp.async.commit_group;");
    // group 1: Bs2 (streams in while stage 1 computes)
    #pragma unroll
    for (int j = 0; j < 7; j++) {
        int c = tid + j*512;
        if (c < 3328) {
            int k = c >> 5, nch = (c & 31) * 4;
            int bytes = 0;
            if (k < HH) {
                bytes = (HH - nch) * 4;
                bytes = bytes < 0 ? 0 : (bytes > 16 ? 16 : bytes);
            }
            const float* src = bytes ? (w2 + k*HH + nch) : w2;
            cp16(Bs2 + k*FB2_S + nch, src, bytes);
        }
    }
    asm volatile("cp.async.commit_group;");
    // zero Hs pad cols
    for (int r = tid; r < 256; r += 512) {
        Hs[r*FHS_S + 100] = 0.f; Hs[r*FHS_S + 101] = 0.f;
        Hs[r*FHS_S + 102] = 0.f; Hs[r*FHS_S + 103] = 0.f;
    }
    asm volatile("cp.async.wait_group 1;");     // As + Bs1 ready
    __syncthreads();

    float acc[4][4][4] = {};

    // ---- Stage 1: K=16 (2 k8 steps) ----
    #pragma unroll
    for (int k8 = 0; k8 < 2; k8++) {
        int k0 = k8 * 8;
        uint32_t a[4][4], b[4][2];
        #pragma unroll
        for (int t2 = 0; t2 < 4; t2++) {
            int row = wm + t2*16 + gr;
            a[t2][0] = __float_as_uint(As[row*FAS_S     + k0 + tg]);
            a[t2][1] = __float_as_uint(As[(row+8)*FAS_S + k0 + tg]);
            a[t2][2] = __float_as_uint(As[row*FAS_S     + k0 + 4 + tg]);
            a[t2][3] = __float_as_uint(As[(row+8)*FAS_S + k0 + 4 + tg]);
        }
        #pragma unroll
        for (int j = 0; j < 4; j++) {
            int col = wn + j*8 + gr;
            b[j][0] = __float_as_uint(Bs1[(k0 + tg)*FB1_S     + col]);
            b[j][1] = __float_as_uint(Bs1[(k0 + 4 + tg)*FB1_S + col]);
        }
        #pragma unroll
        for (int t2 = 0; t2 < 4; t2++)
            #pragma unroll
            for (int j = 0; j < 4; j++)
                mma_tf32(acc[t2][j], a[t2], b[j]);
    }

    // ---- epilogue 1: h1 -> Hs (bias+relu+tf32), reset acc ----
    #pragma unroll
    for (int t2 = 0; t2 < 4; t2++) {
        #pragma unroll
        for (int j = 0; j < 4; j++) {
            #pragma unroll
            for (int h = 0; h < 2; h++) {
                int row = wm + t2*16 + gr + h*8;
                #pragma unroll
                for (int q = 0; q < 2; q++) {
                    int cn = wn + j*8 + tg*2 + q;
                    if (cn < HH) {
                        float v = fmaxf(acc[t2][j][h*2 + q] + bias1[cn], 0.f);
                        Hs[row*FHS_S + cn] = f2tf32f(v);
                    }
                }
            }
            #pragma unroll
            for (int q = 0; q < 4; q++) acc[t2][j][q] = 0.f;
        }
    }
    asm volatile("cp.async.wait_group 0;");     // Bs2 ready
    __syncthreads();

    // ---- Stage 2: K=100 padded to 104 (13 k8 steps) ----
    #pragma unroll
    for (int k8 = 0; k8 < 13; k8++) {
        int k0 = k8 * 8;
        uint32_t a[4][4], b[4][2];
        #pragma unroll
        for (int t2 = 0; t2 < 4; t2++) {
            int row = wm + t2*16 + gr;
            a[t2][0] = __float_as_uint(Hs[row*FHS_S     + k0 + tg]);
            a[t2][1] = __float_as_uint(Hs[(row+8)*FHS_S + k0 + tg]);
            a[t2][2] = __float_as_uint(Hs[row*FHS_S     + k0 + 4 + tg]);
            a[t2][3] = __float_as_uint(Hs[(row+8)*FHS_S + k0 + 4 + tg]);
        }
        #pragma unroll
        for (int j = 0; j < 4; j++) {
            int col = wn + j*8 + gr;
            b[j][0] = __float_as_uint(Bs2[(k0 + tg)*FB2_S     + col]);
            b[j][1] = __float_as_uint(Bs2[(k0 + 4 + tg)*FB2_S + col]);
        }
        #pragma unroll
        for (int t2 = 0; t2 < 4; t2++)
            #pragma unroll
            for (int j = 0; j < 4; j++)
                mma_tf32(acc[t2][j], a[t2], b[j]);
    }

    // ---- epilogue 2: h2 -> global ----
    #pragma unroll
    for (int t2 = 0; t2 < 4; t2++) {
        #pragma unroll
        for (int j = 0; j < 4; j++) {
            #pragma unroll
            for (int h = 0; h < 2; h++) {
                int row = m0 + wm + t2*16 + gr + h*8;
                #pragma unroll
                for (int q = 0; q < 2; q++) {
                    int cn = wn + j*8 + tg*2 + q;
                    if (cn < HH)
                        C[(size_t)row*HH + cn] = fmaxf(acc[t2][j][h*2 + q] + bias2[cn], 0.f);
                }
            }
        }
    }
}

// ---------------- multi-node fused TP, software-pipelined (R13, kept) ----------------
template<int LAYER, int NPC, int THREADS>
__global__ void __launch_bounds__(THREADS)
node_tp(const int* __restrict__ nbr, const int* __restrict__ charges,
        const float* __restrict__ h2, const float* __restrict__ w3r) {
    constexpr int F     = (LAYER==1) ? 4   : (LAYER==2) ? 120 : 24;
    constexpr int WTOT  = (LAYER==1) ? 32  : (LAYER==2) ? 832 : 768;
    constexpr int NSLOT = (LAYER==3) ? 32  : 48;
    constexpr int KG    = (THREADS / NSLOT) > 10 ? 10 : (THREADS / NSLOT);
    constexpr int MF    = HH * F;
    constexpr int FT    = (LAYER==2) ? 12 : (LAYER==3) ? 8 : 4;
    constexpr int NFG   = F / FT;
    constexpr int NCT   = 50 * NFG;

    extern __shared__ float sm[];
    float* h2s  = sm;                        // 2 x 1600
    float* zsA  = h2s + 2*16*HH;             // 2 x 16*F
    float* Ms   = zsA + 2*16*F;              // NPC*MF
    float* part = Ms + NPC*MF;               // KG*NSLOT*NPC
    float* gsm  = part + KG*NSLOT*NPC;       // NPC*8

    const int tid = threadIdx.x;
    const int nbase = blockIdx.x * NPC;

    const float* __restrict__ f0in = (LAYER==2) ? g_f0a : g_f0b;
    const float* __restrict__ f1in = (LAYER==2) ? g_f1a : g_f1b;
    float* f0out = (LAYER==2) ? g_f0b : g_f0a;
    float* f1out = (LAYER==2) ? g_f1b : g_f1a;

    auto stage_h2 = [&](int p, int buf) {
        float* dst = h2s + buf*1600;
        const float* src = h2 + (size_t)(nbase+p)*KK*HH;
        for (int i = tid; i < 400; i += THREADS)
            cp16(dst + i*4, src + i*4, 16);
        asm volatile("cp.async.commit_group;");
    };
    auto gather_z = [&](int p, int buf) {
        float* zb = zsA + buf*(16*F);
        if (tid < 256) {
            int e = tid >> 4, j = tid & 15;
            int ge = (nbase+p)*KK + e;
            int idx = nbr[ge];
            float u0 = g_u[ge*3+0], u1 = g_u[ge*3+1], u2 = g_u[ge*3+2];
            if (LAYER == 1) {
                if (j == 0) {
                    float g0 = 0.5f * ((float)charges[idx] / 94.0f - 0.5f);
                    zb[e*F+0] = g0;
                    zb[e*F+1] = g0*u0; zb[e*F+2] = g0*u1; zb[e*F+3] = g0*u2;
                }
            } else {
                float g0j = 0.5f * f0in[idx*16 + j];
                zb[e*F + j] = g0j;
                if (LAYER == 2) {
                    zb[e*F + 24 + 0*32 + j] = g0j*u0;
                    zb[e*F + 24 + 1*32 + j] = g0j*u1;
                    zb[e*F + 24 + 2*32 + j] = g0j*u2;
                }
                if (j < 8) {
                    float a = 0.5f * f1in[idx*24 + j*3 + 0];
                    float b = 0.5f * f1in[idx*24 + j*3 + 1];
                    float c = 0.5f * f1in[idx*24 + j*3 + 2];
                    zb[e*F + 16 + j] = a*u0 + b*u1 + c*u2;
                    if (LAYER == 2) {
                        zb[e*F + 24 + 0*32 + 16 + j] = a;
                        zb[e*F + 24 + 1*32 + 16 + j] = b;
                        zb[e*F + 24 + 2*32 + 16 + j] = c;
                        zb[e*F + 24 + 0*32 + 24 + j] = b*u2 - c*u1;
                        zb[e*F + 24 + 1*32 + 24 + j] = c*u0 - a*u2;
                        zb[e*F + 24 + 2*32 + 24 + j] = a*u1 - b*u0;
                    }
                }
            }
        }
    };

    stage_h2(0, 0);
    gather_z(0, 0);

    for (int p = 0; p < NPC; p++) {
        int buf = p & 1;
        if (p + 1 < NPC) {
            stage_h2(p + 1, buf ^ 1);
            gather_z(p + 1, buf ^ 1);
            asm volatile("cp.async.wait_group 1;");
        } else {
            asm volatile("cp.async.wait_group 0;");
        }
        __syncthreads();

        const float* hb = h2s + buf*1600;
        const float* zb = zsA + buf*(16*F);
        float* Mp = Ms + p*MF;
        if (tid < NCT) {
            int kg = tid / NFG, fg = tid - kg*NFG;
            int k0 = kg*2, f0 = fg*FT;
            float accm0[FT] = {}, accm1[FT] = {};
            #pragma unroll 4
            for (int e = 0; e < 16; e++) {
                float2 hv = *(const float2*)&hb[e*HH + k0];
                float zv[FT];
                #pragma unroll
                for (int q = 0; q < FT; q += 4) {
                    float4 z4 = *(const float4*)&zb[e*F + f0 + q];
                    zv[q]=z4.x; zv[q+1]=z4.y; zv[q+2]=z4.z; zv[q+3]=z4.w;
                }
                #pragma unroll
                for (int ff = 0; ff < FT; ff++) {
                    accm0[ff] += hv.x * zv[ff];
                    accm1[ff] += hv.y * zv[ff];
                }
            }
            #pragma unroll
            for (int q = 0; q < FT; q += 4) {
                *(float4*)&Mp[k0*F + f0 + q]     = make_float4(accm0[q],accm0[q+1],accm0[q+2],accm0[q+3]);
                *(float4*)&Mp[(k0+1)*F + f0 + q] = make_float4(accm1[q],accm1[q+1],accm1[q+2],accm1[q+3]);
            }
        }
        __syncthreads();
    }

    if (tid < KG*NSLOT) {
        int s = tid % NSLOT, g = tid / NSLOT;
        float acc[NPC];
        #pragma unroll
        for (int p = 0; p < NPC; p++) acc[p] = 0.f;

        for (int k = g; k < HH; k += KG) {
            const float* wr = w3r + k*WTOT;
            if (LAYER == 1) {
                if (s < 24) {
                    float wv = wr[s];
                    #pragma unroll
                    for (int p = 0; p < NPC; p++) acc[p] += wv * Ms[p*MF + k*F + 0];
                } else {
                    int q = s - 24, o = q/3, c = q - o*3;
                    float wv = wr[24 + o];
                    #pragma unroll
                    for (int p = 0; p < NPC; p++) acc[p] += wv * Ms[p*MF + k*F + 1 + c];
                }
            } else if (LAYER == 2) {
                if (s < 24) {
                    float w0[16], w1_[8];
                    #pragma unroll
                    for (int i = 0; i < 16; i++) w0[i] = wr[i*24 + s];
                    #pragma unroll
                    for (int i = 0; i < 8; i++)  w1_[i] = wr[384 + i*24 + s];
                    #pragma unroll
                    for (int p = 0; p < NPC; p++) {
                        const float* Mk = Ms + p*MF + k*F;
                        float4 a0=*(const float4*)(Mk),    a1=*(const float4*)(Mk+4);
                        float4 a2=*(const float4*)(Mk+8),  a3=*(const float4*)(Mk+12);
                        float4 b0=*(const float4*)(Mk+16), b1=*(const float4*)(Mk+20);
                        acc[p]+=w0[0]*a0.x;  acc[p]+=w0[1]*a0.y;  acc[p]+=w0[2]*a0.z;  acc[p]+=w0[3]*a0.w;
                        acc[p]+=w0[4]*a1.x;  acc[p]+=w0[5]*a1.y;  acc[p]+=w0[6]*a1.z;  acc[p]+=w0[7]*a1.w;
                        acc[p]+=w0[8]*a2.x;  acc[p]+=w0[9]*a2.y;  acc[p]+=w0[10]*a2.z; acc[p]+=w0[11]*a2.w;
                        acc[p]+=w0[12]*a3.x; acc[p]+=w0[13]*a3.y; acc[p]+=w0[14]*a3.z; acc[p]+=w0[15]*a3.w;
                        acc[p]+=w1_[0]*b0.x; acc[p]+=w1_[1]*b0.y; acc[p]+=w1_[2]*b0.z; acc[p]+=w1_[3]*b0.w;
                        acc[p]+=w1_[4]*b1.x; acc[p]+=w1_[5]*b1.y; acc[p]+=w1_[6]*b1.z; acc[p]+=w1_[7]*b1.w;
                    }
                } else {
                    int q = s - 24, o = q/3, c = q - o*3;
                    float wv0[16], wv1[8], wv2[8];
                    #pragma unroll
                    for (int i = 0; i < 16; i++) wv0[i] = wr[576 + i*8 + o];
                    #pragma unroll
                    for (int i = 0; i < 8; i++)  wv1[i] = wr[704 + i*8 + o];
                    #pragma unroll
                    for (int i = 0; i < 8; i++)  wv2[i] = wr[768 + i*8 + o];
                    #pragma unroll
                    for (int p = 0; p < NPC; p++) {
                        const float* Mk = Ms + p*MF + k*F + 24 + c*32;
                        float4 a0=*(const float4*)(Mk),    a1=*(const float4*)(Mk+4);
                        float4 a2=*(const float4*)(Mk+8),  a3=*(const float4*)(Mk+12);
                        float4 b0=*(const float4*)(Mk+16), b1=*(const float4*)(Mk+20);
                        float4 c0=*(const float4*)(Mk+24), c1=*(const float4*)(Mk+28);
                        acc[p]+=wv0[0]*a0.x;  acc[p]+=wv0[1]*a0.y;  acc[p]+=wv0[2]*a0.z;  acc[p]+=wv0[3]*a0.w;
                        acc[p]+=wv0[4]*a1.x;  acc[p]+=wv0[5]*a1.y;  acc[p]+=wv0[6]*a1.z;  acc[p]+=wv0[7]*a1.w;
                        acc[p]+=wv0[8]*a2.x;  acc[p]+=wv0[9]*a2.y;  acc[p]+=wv0[10]*a2.z; acc[p]+=wv0[11]*a2.w;
                        acc[p]+=wv0[12]*a3.x; acc[p]+=wv0[13]*a3.y; acc[p]+=wv0[14]*a3.z; acc[p]+=wv0[15]*a3.w;
                        acc[p]+=wv1[0]*b0.x;  acc[p]+=wv1[1]*b0.y;  acc[p]+=wv1[2]*b0.z;  acc[p]+=wv1[3]*b0.w;
                        acc[p]+=wv1[4]*b1.x;  acc[p]+=wv1[5]*b1.y;  acc[p]+=wv1[6]*b1.z;  acc[p]+=wv1[7]*b1.w;
                        acc[p]+=wv2[0]*c0.x;  acc[p]+=wv2[1]*c0.y;  acc[p]+=wv2[2]*c0.z;  acc[p]+=wv2[3]*c0.w;
                        acc[p]+=wv2[4]*c1.x;  acc[p]+=wv2[5]*c1.y;  acc[p]+=wv2[6]*c1.z;  acc[p]+=wv2[7]*c1.w;
                    }
                }
            } else {
                float w0[16], w1_[8];
                #pragma unroll
                for (int i = 0; i < 16; i++) w0[i] = wr[i*32 + s];
                #pragma unroll
                for (int i = 0; i < 8; i++)  w1_[i] = wr[512 + i*32 + s];
                #pragma unroll
                for (int p = 0; p < NPC; p++) {
                    const float* Mk = Ms + p*MF + k*F;
                    float4 a0=*(const float4*)(Mk),    a1=*(const float4*)(Mk+4);
                    float4 a2=*(const float4*)(Mk+8),  a3=*(const float4*)(Mk+12);
                    float4 b0=*(const float4*)(Mk+16), b1=*(const float4*)(Mk+20);
                    acc[p]+=w0[0]*a0.x;  acc[p]+=w0[1]*a0.y;  acc[p]+=w0[2]*a0.z;  acc[p]+=w0[3]*a0.w;
                    acc[p]+=w0[4]*a1.x;  acc[p]+=w0[5]*a1.y;  acc[p]+=w0[6]*a1.z;  acc[p]+=w0[7]*a1.w;
                    acc[p]+=w0[8]*a2.x;  acc[p]+=w0[9]*a2.y;  acc[p]+=w0[10]*a2.z; acc[p]+=w0[11]*a2.w;
                    acc[p]+=w0[12]*a3.x; acc[p]+=w0[13]*a3.y; acc[p]+=w0[14]*a3.z; acc[p]+=w0[15]*a3.w;
                    acc[p]+=w1_[0]*b0.x; acc[p]+=w1_[1]*b0.y; acc[p]+=w1_[2]*b0.z; acc[p]+=w1_[3]*b0.w;
                    acc[p]+=w1_[4]*b1.x; acc[p]+=w1_[5]*b1.y; acc[p]+=w1_[6]*b1.z; acc[p]+=w1_[7]*b1.w;
                }
            }
        }
        #pragma unroll
        for (int p = 0; p < NPC; p++)
            part[tid*NPC + p] = acc[p];
    }
    __syncthreads();

    for (int t2 = tid; t2 < NPC*NSLOT; t2 += THREADS) {
        int p = t2 / NSLOT, s = t2 % NSLOT;
        float m = 0.f;
        #pragma unroll
        for (int g = 0; g < KG; g++) m += part[(g*NSLOT + s)*NPC + p];
        m *= (1.0f/16.0f);
        int n = nbase + p;
        if (LAYER == 3) {
            f0out[n*32 + s] = fmaxf(m, 0.f);
        } else {
            part[s*NPC + p] = m;
            if (s >= 16 && s < 24)
                gsm[p*8 + (s-16)] = 1.0f / (1.0f + expf(-m));
        }
    }
    if (LAYER != 3) {
        __syncthreads();
        for (int t2 = tid; t2 < NPC*NSLOT; t2 += THREADS) {
            int p = t2 / NSLOT, s = t2 % NSLOT;
            int n = nbase + p;
            float m = part[s*NPC + p];
            if (s < 16) {
                f0out[n*16 + s] = fmaxf(m, 0.f);
            } else if (s >= 24) {
                int q = s - 24, o = q/3, c = q - o*3;
                f1out[(n*8 + o)*3 + c] = m * gsm[p*8 + o];
            }
        }
    }
}

// ---------------- final reduce ----------------
__global__ void reduce_kernel(float* __restrict__ out) {
    __shared__ float red[256];
    int j = blockIdx.x;
    float s = 0.f;
    for (int n = threadIdx.x; n < NN; n += 256) s += g_f0a[n*32 + j];
    red[threadIdx.x] = s;
    __syncthreads();
    for (int w = 128; w > 0; w >>= 1) {
        if (threadIdx.x < w) red[threadIdx.x] += red[threadIdx.x + w];
        __syncthreads();
    }
    if (threadIdx.x == 0) out[j] = red[0] * (1.0f/NN);
}

// ---------------- host ----------------
extern "C" void kernel_launch(void* const* d_in, const int* in_sizes, int n_in,
                              void* d_out, int out_size) {
    const float* radii   = (const float*)d_in[0];
    const int*   nbr     = (const int*)d_in[1];
    const int*   charges = (const int*)d_in[2];

    void* p;
    cudaGetSymbolAddress(&p, g_basis); float* basis = (float*)p;
    cudaGetSymbolAddress(&p, g_h2A);   float* h2A   = (float*)p;
    cudaGetSymbolAddress(&p, g_w1tA);  float* w1tA  = (float*)p;
    cudaGetSymbolAddress(&p, g_w2tA);  float* w2tA  = (float*)p;
    cudaGetSymbolAddress(&p, g_w3rA);  float* w3rA  = (float*)p;

    const int fm_smem = FM_SMEM_FLOATS * 4;   // 192256
    cudaFuncSetAttribute(fused_mlp, cudaFuncAttributeMaxDynamicSharedMemorySize, fm_smem);

    const int ns1 = (3200 + 2*16*4   + 8*100*4   + 5*48*8  + 64) * 4;
    const int ns2 = (3200 + 2*16*120 + 2*100*120 + 10*48*2 + 16) * 4;
    const int ns3 = (3200 + 2*16*24  + 8*100*24  + 8*32*8  + 64) * 4;
    cudaFuncSetAttribute((const void*)node_tp<1,8,256>, cudaFuncAttributeMaxDynamicSharedMemorySize, ns1);
    cudaFuncSetAttribute((const void*)node_tp<2,2,512>, cudaFuncAttributeMaxDynamicSharedMemorySize, ns2);
    cudaFuncSetAttribute((const void*)node_tp<3,8,256>, cudaFuncAttributeMaxDynamicSharedMemorySize, ns3);

    prep_kernel<<<(EE+255)/256, 256>>>(radii);

    prep_weights<<<(198000+255)/256, 256>>>(
        (const float*)d_in[3],  (const float*)d_in[5],  (const float*)d_in[7],
        (const float*)d_in[8],  (const float*)d_in[10], (const float*)d_in[12],
        (const float*)d_in[13], (const float*)d_in[15], (const float*)d_in[17]);

    Bias3 b1 = {{ (const float*)d_in[4],  (const float*)d_in[9],  (const float*)d_in[14] }};
    Bias3 b2 = {{ (const float*)d_in[6],  (const float*)d_in[11], (const float*)d_in[16] }};

    dim3 gridF(1, EE/256, 3);
    fused_mlp<<<gridF, 512, fm_smem>>>(basis, w1tA, w2tA, b1, b2, h2A);

    node_tp<1,8,256><<<NN/8, 256, ns1>>>(nbr, charges, h2A,                   w3rA);
    node_tp<2,2,512><<<NN/2, 512, ns2>>>(nbr, charges, h2A + (size_t)EE*HH,   w3rA + 83200);
    node_tp<3,8,256><<<NN/8, 256, ns3>>>(nbr, charges, h2A + (size_t)2*EE*HH, w3rA + 2*83200);

    reduce_kernel<<<32, 256>>>((float*)d_out);
}

// round 15
// speedup vs baseline: 1.0776x; 1.0776x over previous
#include <cuda_runtime.h>
#include <math.h>
#include <stdint.h>

#define NN 10000
#define KK 16
#define EE (NN*KK)
#define HH 100
#define NB 10
#define NBP 16

// ---------------- scratch ----------------
__device__ float g_basis[EE*NBP];
__device__ float g_u[EE*3];
__device__ float g_h2A[3*EE*HH];
__device__ float g_f0a[NN*32];
__device__ float g_f0b[NN*32];
__device__ float g_f1a[NN*24];
__device__ float g_f1b[NN*24];
__device__ float g_w1tA[3*NBP*HH];
__device__ float g_w2tA[3*HH*HH];
__device__ float g_w3rA[3*83200];

struct Bias3 { const float* b[3]; };

// ---------------- helpers ----------------
__device__ __forceinline__ float f2tf32f(float v) {
    uint32_t r;
    asm("cvt.rna.tf32.f32 %0, %1;" : "=r"(r) : "f"(v));
    return __uint_as_float(r);
}

__device__ __forceinline__ void mma_tf32(float* c, const uint32_t* a, const uint32_t* b) {
    asm volatile("mma.sync.aligned.m16n8k8.row.col.f32.tf32.tf32.f32 "
        "{%0,%1,%2,%3}, {%4,%5,%6,%7}, {%8,%9}, {%0,%1,%2,%3};"
        : "+f"(c[0]), "+f"(c[1]), "+f"(c[2]), "+f"(c[3])
        : "r"(a[0]), "r"(a[1]), "r"(a[2]), "r"(a[3]), "r"(b[0]), "r"(b[1]));
}

__device__ __forceinline__ void cp16(void* dst_smem, const void* src, int bytes) {
    uint32_t d = (uint32_t)__cvta_generic_to_shared(dst_smem);
    asm volatile("cp.async.cg.shared.global [%0], [%1], 16, %2;"
                 :: "r"(d), "l"(src), "r"(bytes));
}

// ---------------- prep ----------------
__global__ void prep_kernel(const float* __restrict__ radii) {
    int e = blockIdx.x*blockDim.x + threadIdx.x;
    if (e >= EE) return;
    float x = radii[e*3+0], y = radii[e*3+1], z = radii[e*3+2];
    float r = sqrtf(x*x + y*y + z*z);
    float inv = 1.0f / (r + 1e-8f);
    g_u[e*3+0] = x*inv; g_u[e*3+1] = y*inv; g_u[e*3+2] = z*inv;
    float rs = r * 1.8f;
    #pragma unroll
    for (int b = 0; b < NBP; b++) {
        float v = 0.f;
        if (b < NB) {
            float d = rs - (float)b;
            if (fabsf(d) < 1.0f) {
                float c = cospif(0.5f * d);
                v = f2tf32f(c * c);
            }
        }
        g_basis[e*NBP + b] = v;
    }
}

// ---------------- fused weight prep ----------------
__global__ void prep_weights(
    const float* __restrict__ w1a, const float* __restrict__ w2a, const float* __restrict__ w3a,
    const float* __restrict__ w1b, const float* __restrict__ w2b, const float* __restrict__ w3b,
    const float* __restrict__ w1c, const float* __restrict__ w2c, const float* __restrict__ w3c) {
    int i = blockIdx.x*blockDim.x + threadIdx.x;
    if (i < 4800) {
        int l = i / 1600, r = i - l*1600;
        int row = r / HH;
        const float* s = (l==0) ? w1a : (l==1) ? w1b : w1c;
        g_w1tA[i] = (row < NB) ? f2tf32f(s[r]) : 0.f;
    } else if (i < 34800) {
        int j = i - 4800;
        int l = j / 10000, r = j - l*10000;
        const float* s = (l==0) ? w2a : (l==1) ? w2b : w2c;
        g_w2tA[j] = f2tf32f(s[r]);
    } else {
        int j = i - 34800;
        if (j < 3200) {
            g_w3rA[j] = w3a[j];
        } else if (j < 3200 + 83200) {
            int r = j - 3200;
            int k = r / 832, d = r - k*832;
            int src;
            if      (d < 384) { int o=d%24,      i2=d/24;       src = o*16 + i2; }
            else if (d < 576) { int t=d-384; int o=t%24, i2=t/24; src = 384 + o*8 + i2; }
            else if (d < 704) { int t=d-576; int o=t%8,  i2=t/8;  src = 576 + o*16 + i2; }
            else if (d < 768) { int t=d-704; int o=t%8,  i2=t/8;  src = 704 + o*8 + i2; }
            else              { int t=d-768; int o=t%8,  i2=t/8;  src = 768 + o*8 + i2; }
            g_w3rA[83200 + r] = w3b[k*832 + src];
        } else if (j < 3200 + 83200 + 76800) {
            int r = j - 3200 - 83200;
            int k = r / 768, d = r - k*768;
            int src;
            if (d < 512) { int o=d%32, i2=d/32; src = o*16 + i2; }
            else         { int t=d-512; int o=t%32, i2=t/32; src = 512 + o*8 + i2; }
            g_w3rA[2*83200 + r] = w3c[k*768 + src];
        }
    }
}

// ---------------- fused radial MLP (exact R12 version) ----------------
#define FAS_S 20
#define FB1_S 136
#define FHS_S 104
#define FB2_S 136
#define FM_SMEM_FLOATS (256*FAS_S + 16*FB1_S + 256*FHS_S + 104*FB2_S)

__global__ void __launch_bounds__(512, 1)
fused_mlp(const float* __restrict__ basis,
          const float* __restrict__ w1A, const float* __restrict__ w2A,
          Bias3 b1, Bias3 b2,
          float* __restrict__ h2A) {
    extern __shared__ float smem[];
    float* As  = smem;                  // 256 x 20
    float* Bs1 = As + 256*FAS_S;        // 16 x 136
    float* Hs  = Bs1 + 16*FB1_S;        // 256 x 104
    float* Bs2 = Hs + 256*FHS_S;        // 104 x 136

    const int z = blockIdx.z;
    const float* w1 = w1A + z*NBP*HH;
    const float* w2 = w2A + z*HH*HH;
    const float* bias1 = b1.b[z];
    const float* bias2 = b2.b[z];
    float* C = h2A + (size_t)z*EE*HH;

    const int tid = threadIdx.x;
    const int lane = tid & 31, wid = tid >> 5;
    const int wm = (wid & 3) * 64;
    const int wn = (wid >> 2) * 32;
    const int m0 = blockIdx.y * 256;
    const int gr = lane >> 2, tg = lane & 3;

    #pragma unroll
    for (int j = 0; j < 2; j++) {                       // As: 256x16
        int c = tid + j*512;
        int row = c >> 2, kch = (c & 3) * 4;
        cp16(As + row*FAS_S + kch, basis + (size_t)(m0+row)*NBP + kch, 16);
    }
    {                                                    // Bs1: 16x128 (pad n>=100)
        int k = tid >> 5, nch = (tid & 31) * 4;
        int bytes = (HH - nch) * 4;
        bytes = bytes < 0 ? 0 : (bytes > 16 ? 16 : bytes);
        const float* src = bytes ? (w1 + k*HH + nch) : w1;
        cp16(Bs1 + k*FB1_S + nch, src, bytes);
    }
    #pragma unroll
    for (int j = 0; j < 7; j++) {                       // Bs2: 104x128 (zero rows>=100, cols>=100)
        int c = tid + j*512;
        if (c < 3328) {
            int k = c >> 5, nch = (c & 31) * 4;
            int bytes = 0;
            if (k < HH) {
                bytes = (HH - nch) * 4;
                bytes = bytes < 0 ? 0 : (bytes > 16 ? 16 : bytes);
            }
            const float* src = bytes ? (w2 + k*HH + nch) : w2;
            cp16(Bs2 + k*FB2_S + nch, src, bytes);
        }
    }
    asm volatile("cp.async.commit_group;");
    for (int r = tid; r < 256; r += 512) {
        Hs[r*FHS_S + 100] = 0.f; Hs[r*FHS_S + 101] = 0.f;
        Hs[r*FHS_S + 102] = 0.f; Hs[r*FHS_S + 103] = 0.f;
    }
    asm volatile("cp.async.wait_group 0;");
    __syncthreads();

    float acc[4][4][4] = {};

    #pragma unroll
    for (int k8 = 0; k8 < 2; k8++) {
        int k0 = k8 * 8;
        uint32_t a[4][4], b[4][2];
        #pragma unroll
        for (int t2 = 0; t2 < 4; t2++) {
            int row = wm + t2*16 + gr;
            a[t2][0] = __float_as_uint(As[row*FAS_S     + k0 + tg]);
            a[t2][1] = __float_as_uint(As[(row+8)*FAS_S + k0 + tg]);
            a[t2][2] = __float_as_uint(As[row*FAS_S     + k0 + 4 + tg]);
            a[t2][3] = __float_as_uint(As[(row+8)*FAS_S + k0 + 4 + tg]);
        }
        #pragma unroll
        for (int j = 0; j < 4; j++) {
            int col = wn + j*8 + gr;
            b[j][0] = __float_as_uint(Bs1[(k0 + tg)*FB1_S     + col]);
            b[j][1] = __float_as_uint(Bs1[(k0 + 4 + tg)*FB1_S + col]);
        }
        #pragma unroll
        for (int t2 = 0; t2 < 4; t2++)
            #pragma unroll
            for (int j = 0; j < 4; j++)
                mma_tf32(acc[t2][j], a[t2], b[j]);
    }

    #pragma unroll
    for (int t2 = 0; t2 < 4; t2++) {
        #pragma unroll
        for (int j = 0; j < 4; j++) {
            #pragma unroll
            for (int h = 0; h < 2; h++) {
                int row = wm + t2*16 + gr + h*8;
                #pragma unroll
                for (int q = 0; q < 2; q++) {
                    int cn = wn + j*8 + tg*2 + q;
                    if (cn < HH) {
                        float v = fmaxf(acc[t2][j][h*2 + q] + bias1[cn], 0.f);
                        Hs[row*FHS_S + cn] = f2tf32f(v);
                    }
                }
            }
            #pragma unroll
            for (int q = 0; q < 4; q++) acc[t2][j][q] = 0.f;
        }
    }
    __syncthreads();

    #pragma unroll
    for (int k8 = 0; k8 < 13; k8++) {
        int k0 = k8 * 8;
        uint32_t a[4][4], b[4][2];
        #pragma unroll
        for (int t2 = 0; t2 < 4; t2++) {
            int row = wm + t2*16 + gr;
            a[t2][0] = __float_as_uint(Hs[row*FHS_S     + k0 + tg]);
            a[t2][1] = __float_as_uint(Hs[(row+8)*FHS_S + k0 + tg]);
            a[t2][2] = __float_as_uint(Hs[row*FHS_S     + k0 + 4 + tg]);
            a[t2][3] = __float_as_uint(Hs[(row+8)*FHS_S + k0 + 4 + tg]);
        }
        #pragma unroll
        for (int j = 0; j < 4; j++) {
            int col = wn + j*8 + gr;
            b[j][0] = __float_as_uint(Bs2[(k0 + tg)*FB2_S     + col]);
            b[j][1] = __float_as_uint(Bs2[(k0 + 4 + tg)*FB2_S + col]);
        }
        #pragma unroll
        for (int t2 = 0; t2 < 4; t2++)
            #pragma unroll
            for (int j = 0; j < 4; j++)
                mma_tf32(acc[t2][j], a[t2], b[j]);
    }

    #pragma unroll
    for (int t2 = 0; t2 < 4; t2++) {
        #pragma unroll
        for (int j = 0; j < 4; j++) {
            #pragma unroll
            for (int h = 0; h < 2; h++) {
                int row = m0 + wm + t2*16 + gr + h*8;
                #pragma unroll
                for (int q = 0; q < 2; q++) {
                    int cn = wn + j*8 + tg*2 + q;
                    if (cn < HH)
                        C[(size_t)row*HH + cn] = fmaxf(acc[t2][j][h*2 + q] + bias2[cn], 0.f);
                }
            }
        }
    }
}

// ---------------- multi-node fused TP; PIPE selects double-buffered staging ----------------
template<int LAYER, int NPC, int THREADS, bool PIPE>
__global__ void __launch_bounds__(THREADS)
node_tp(const int* __restrict__ nbr, const int* __restrict__ charges,
        const float* __restrict__ h2, const float* __restrict__ w3r) {
    constexpr int F     = (LAYER==1) ? 4   : (LAYER==2) ? 120 : 24;
    constexpr int WTOT  = (LAYER==1) ? 32  : (LAYER==2) ? 832 : 768;
    constexpr int NSLOT = (LAYER==3) ? 32  : 48;
    constexpr int KG    = (THREADS / NSLOT) > 10 ? 10 : (THREADS / NSLOT);
    constexpr int MF    = HH * F;
    constexpr int FT    = (LAYER==2) ? 12 : (LAYER==3) ? 8 : 4;
    constexpr int NFG   = F / FT;
    constexpr int NCT   = 50 * NFG;
    constexpr int NBUF  = PIPE ? 2 : 1;

    extern __shared__ float sm[];
    float* h2s  = sm;                        // NBUF x 1600
    float* zsA  = h2s + NBUF*16*HH;          // NBUF x 16*F
    float* Ms   = zsA + NBUF*16*F;           // NPC*MF
    float* part = Ms + NPC*MF;               // KG*NSLOT*NPC
    float* gsm  = part + KG*NSLOT*NPC;       // NPC*8

    const int tid = threadIdx.x;
    const int nbase = blockIdx.x * NPC;

    const float* __restrict__ f0in = (LAYER==2) ? g_f0a : g_f0b;
    const float* __restrict__ f1in = (LAYER==2) ? g_f1a : g_f1b;
    float* f0out = (LAYER==2) ? g_f0b : g_f0a;
    float* f1out = (LAYER==2) ? g_f1b : g_f1a;

    auto stage_h2_async = [&](int p, int buf) {
        float* dst = h2s + buf*1600;
        const float* src = h2 + (size_t)(nbase+p)*KK*HH;
        for (int i = tid; i < 400; i += THREADS)
            cp16(dst + i*4, src + i*4, 16);
        asm volatile("cp.async.commit_group;");
    };
    auto stage_h2_plain = [&](int p) {
        const float4* src = (const float4*)(h2 + (size_t)(nbase+p)*KK*HH);
        float4* dst = (float4*)h2s;
        for (int i = tid; i < 400; i += THREADS) dst[i] = src[i];
    };
    auto gather_z = [&](int p, int buf) {
        float* zb = zsA + buf*(16*F);
        if (tid < 256) {
            int e = tid >> 4, j = tid & 15;
            int ge = (nbase+p)*KK + e;
            int idx = nbr[ge];
            float u0 = g_u[ge*3+0], u1 = g_u[ge*3+1], u2 = g_u[ge*3+2];
            if (LAYER == 1) {
                if (j == 0) {
                    float g0 = 0.5f * ((float)charges[idx] / 94.0f - 0.5f);
                    zb[e*F+0] = g0;
                    zb[e*F+1] = g0*u0; zb[e*F+2] = g0*u1; zb[e*F+3] = g0*u2;
                }
            } else {
                float g0j = 0.5f * f0in[idx*16 + j];
                zb[e*F + j] = g0j;
                if (LAYER == 2) {
                    zb[e*F + 24 + 0*32 + j] = g0j*u0;
                    zb[e*F + 24 + 1*32 + j] = g0j*u1;
                    zb[e*F + 24 + 2*32 + j] = g0j*u2;
                }
                if (j < 8) {
                    float a = 0.5f * f1in[idx*24 + j*3 + 0];
                    float b = 0.5f * f1in[idx*24 + j*3 + 1];
                    float c = 0.5f * f1in[idx*24 + j*3 + 2];
                    zb[e*F + 16 + j] = a*u0 + b*u1 + c*u2;
                    if (LAYER == 2) {
                        zb[e*F + 24 + 0*32 + 16 + j] = a;
                        zb[e*F + 24 + 1*32 + 16 + j] = b;
                        zb[e*F + 24 + 2*32 + 16 + j] = c;
                        zb[e*F + 24 + 0*32 + 24 + j] = b*u2 - c*u1;
                        zb[e*F + 24 + 1*32 + 24 + j] = c*u0 - a*u2;
                        zb[e*F + 24 + 2*32 + 24 + j] = a*u1 - b*u0;
                    }
                }
            }
        }
    };
    auto phase_c = [&](int p, int buf) {
        const float* hb = h2s + buf*1600;
        const float* zb = zsA + buf*(16*F);
        float* Mp = Ms + p*MF;
        if (tid < NCT) {
            int kg = tid / NFG, fg = tid - kg*NFG;
            int k0 = kg*2, f0 = fg*FT;
            float accm0[FT] = {}, accm1[FT] = {};
            #pragma unroll 4
            for (int e = 0; e < 16; e++) {
                float2 hv = *(const float2*)&hb[e*HH + k0];
                float zv[FT];
                #pragma unroll
                for (int q = 0; q < FT; q += 4) {
                    float4 z4 = *(const float4*)&zb[e*F + f0 + q];
                    zv[q]=z4.x; zv[q+1]=z4.y; zv[q+2]=z4.z; zv[q+3]=z4.w;
                }
                #pragma unroll
                for (int ff = 0; ff < FT; ff++) {
                    accm0[ff] += hv.x * zv[ff];
                    accm1[ff] += hv.y * zv[ff];
                }
            }
            #pragma unroll
            for (int q = 0; q < FT; q += 4) {
                *(float4*)&Mp[k0*F + f0 + q]     = make_float4(accm0[q],accm0[q+1],accm0[q+2],accm0[q+3]);
                *(float4*)&Mp[(k0+1)*F + f0 + q] = make_float4(accm1[q],accm1[q+1],accm1[q+2],accm1[q+3]);
            }
        }
    };

    if (PIPE) {
        stage_h2_async(0, 0);
        gather_z(0, 0);
        for (int p = 0; p < NPC; p++) {
            int buf = p & 1;
            if (p + 1 < NPC) {
                stage_h2_async(p + 1, buf ^ 1);
                gather_z(p + 1, buf ^ 1);
                asm volatile("cp.async.wait_group 1;");
            } else {
                asm volatile("cp.async.wait_group 0;");
            }
            __syncthreads();
            phase_c(p, buf);
            __syncthreads();
        }
    } else {
        for (int p = 0; p < NPC; p++) {
            gather_z(p, 0);
            stage_h2_plain(p);
            __syncthreads();
            phase_c(p, 0);
            __syncthreads();
        }
    }

    // ---- Phase D ----
    if (tid < KG*NSLOT) {
        int s = tid % NSLOT, g = tid / NSLOT;
        float acc[NPC];
        #pragma unroll
        for (int p = 0; p < NPC; p++) acc[p] = 0.f;

        for (int k = g; k < HH; k += KG) {
            const float* wr = w3r + k*WTOT;
            if (LAYER == 1) {
                if (s < 24) {
                    float wv = wr[s];
                    #pragma unroll
                    for (int p = 0; p < NPC; p++) acc[p] += wv * Ms[p*MF + k*F + 0];
                } else {
                    int q = s - 24, o = q/3, c = q - o*3;
                    float wv = wr[24 + o];
                    #pragma unroll
                    for (int p = 0; p < NPC; p++) acc[p] += wv * Ms[p*MF + k*F + 1 + c];
                }
            } else if (LAYER == 2) {
                if (s < 24) {
                    float w0[16], w1_[8];
                    #pragma unroll
                    for (int i = 0; i < 16; i++) w0[i] = wr[i*24 + s];
                    #pragma unroll
                    for (int i = 0; i < 8; i++)  w1_[i] = wr[384 + i*24 + s];
                    #pragma unroll
                    for (int p = 0; p < NPC; p++) {
                        const float* Mk = Ms + p*MF + k*F;
                        float4 a0=*(const float4*)(Mk),    a1=*(const float4*)(Mk+4);
                        float4 a2=*(const float4*)(Mk+8),  a3=*(const float4*)(Mk+12);
                        float4 b0=*(const float4*)(Mk+16), b1=*(const float4*)(Mk+20);
                        acc[p]+=w0[0]*a0.x;  acc[p]+=w0[1]*a0.y;  acc[p]+=w0[2]*a0.z;  acc[p]+=w0[3]*a0.w;
                        acc[p]+=w0[4]*a1.x;  acc[p]+=w0[5]*a1.y;  acc[p]+=w0[6]*a1.z;  acc[p]+=w0[7]*a1.w;
                        acc[p]+=w0[8]*a2.x;  acc[p]+=w0[9]*a2.y;  acc[p]+=w0[10]*a2.z; acc[p]+=w0[11]*a2.w;
                        acc[p]+=w0[12]*a3.x; acc[p]+=w0[13]*a3.y; acc[p]+=w0[14]*a3.z; acc[p]+=w0[15]*a3.w;
                        acc[p]+=w1_[0]*b0.x; acc[p]+=w1_[1]*b0.y; acc[p]+=w1_[2]*b0.z; acc[p]+=w1_[3]*b0.w;
                        acc[p]+=w1_[4]*b1.x; acc[p]+=w1_[5]*b1.y; acc[p]+=w1_[6]*b1.z; acc[p]+=w1_[7]*b1.w;
                    }
                } else {
                    int q = s - 24, o = q/3, c = q - o*3;
                    float wv0[16], wv1[8], wv2[8];
                    #pragma unroll
                    for (int i = 0; i < 16; i++) wv0[i] = wr[576 + i*8 + o];
                    #pragma unroll
                    for (int i = 0; i < 8; i++)  wv1[i] = wr[704 + i*8 + o];
                    #pragma unroll
                    for (int i = 0; i < 8; i++)  wv2[i] = wr[768 + i*8 + o];
                    #pragma unroll
                    for (int p = 0; p < NPC; p++) {
                        const float* Mk = Ms + p*MF + k*F + 24 + c*32;
                        float4 a0=*(const float4*)(Mk),    a1=*(const float4*)(Mk+4);
                        float4 a2=*(const float4*)(Mk+8),  a3=*(const float4*)(Mk+12);
                        float4 b0=*(const float4*)(Mk+16), b1=*(const float4*)(Mk+20);
                        float4 c0=*(const float4*)(Mk+24), c1=*(const float4*)(Mk+28);
                        acc[p]+=wv0[0]*a0.x;  acc[p]+=wv0[1]*a0.y;  acc[p]+=wv0[2]*a0.z;  acc[p]+=wv0[3]*a0.w;
                        acc[p]+=wv0[4]*a1.x;  acc[p]+=wv0[5]*a1.y;  acc[p]+=wv0[6]*a1.z;  acc[p]+=wv0[7]*a1.w;
                        acc[p]+=wv0[8]*a2.x;  acc[p]+=wv0[9]*a2.y;  acc[p]+=wv0[10]*a2.z; acc[p]+=wv0[11]*a2.w;
                        acc[p]+=wv0[12]*a3.x; acc[p]+=wv0[13]*a3.y; acc[p]+=wv0[14]*a3.z; acc[p]+=wv0[15]*a3.w;
                        acc[p]+=wv1[0]*b0.x;  acc[p]+=wv1[1]*b0.y;  acc[p]+=wv1[2]*b0.z;  acc[p]+=wv1[3]*b0.w;
                        acc[p]+=wv1[4]*b1.x;  acc[p]+=wv1[5]*b1.y;  acc[p]+=wv1[6]*b1.z;  acc[p]+=wv1[7]*b1.w;
                        acc[p]+=wv2[0]*c0.x;  acc[p]+=wv2[1]*c0.y;  acc[p]+=wv2[2]*c0.z;  acc[p]+=wv2[3]*c0.w;
                        acc[p]+=wv2[4]*c1.x;  acc[p]+=wv2[5]*c1.y;  acc[p]+=wv2[6]*c1.z;  acc[p]+=wv2[7]*c1.w;
                    }
                }
            } else {
                float w0[16], w1_[8];
                #pragma unroll
                for (int i = 0; i < 16; i++) w0[i] = wr[i*32 + s];
                #pragma unroll
                for (int i = 0; i < 8; i++)  w1_[i] = wr[512 + i*32 + s];
                #pragma unroll
                for (int p = 0; p < NPC; p++) {
                    const float* Mk = Ms + p*MF + k*F;
                    float4 a0=*(const float4*)(Mk),    a1=*(const float4*)(Mk+4);
                    float4 a2=*(const float4*)(Mk+8),  a3=*(const float4*)(Mk+12);
                    float4 b0=*(const float4*)(Mk+16), b1=*(const float4*)(Mk+20);
                    acc[p]+=w0[0]*a0.x;  acc[p]+=w0[1]*a0.y;  acc[p]+=w0[2]*a0.z;  acc[p]+=w0[3]*a0.w;
                    acc[p]+=w0[4]*a1.x;  acc[p]+=w0[5]*a1.y;  acc[p]+=w0[6]*a1.z;  acc[p]+=w0[7]*a1.w;
                    acc[p]+=w0[8]*a2.x;  acc[p]+=w0[9]*a2.y;  acc[p]+=w0[10]*a2.z; acc[p]+=w0[11]*a2.w;
                    acc[p]+=w0[12]*a3.x; acc[p]+=w0[13]*a3.y; acc[p]+=w0[14]*a3.z; acc[p]+=w0[15]*a3.w;
                    acc[p]+=w1_[0]*b0.x; acc[p]+=w1_[1]*b0.y; acc[p]+=w1_[2]*b0.z; acc[p]+=w1_[3]*b0.w;
                    acc[p]+=w1_[4]*b1.x; acc[p]+=w1_[5]*b1.y; acc[p]+=w1_[6]*b1.z; acc[p]+=w1_[7]*b1.w;
                }
            }
        }
        #pragma unroll
        for (int p = 0; p < NPC; p++)
            part[tid*NPC + p] = acc[p];
    }
    __syncthreads();

    // ---- Phase E ----
    for (int t2 = tid; t2 < NPC*NSLOT; t2 += THREADS) {
        int p = t2 / NSLOT, s = t2 % NSLOT;
        float m = 0.f;
        #pragma unroll
        for (int g = 0; g < KG; g++) m += part[(g*NSLOT + s)*NPC + p];
        m *= (1.0f/16.0f);
        int n = nbase + p;
        if (LAYER == 3) {
            f0out[n*32 + s] = fmaxf(m, 0.f);
        } else {
            part[s*NPC + p] = m;
            if (s >= 16 && s < 24)
                gsm[p*8 + (s-16)] = 1.0f / (1.0f + expf(-m));
        }
    }
    if (LAYER != 3) {
        __syncthreads();
        for (int t2 = tid; t2 < NPC*NSLOT; t2 += THREADS) {
            int p = t2 / NSLOT, s = t2 % NSLOT;
            int n = nbase + p;
            float m = part[s*NPC + p];
            if (s < 16) {
                f0out[n*16 + s] = fmaxf(m, 0.f);
            } else if (s >= 24) {
                int q = s - 24, o = q/3, c = q - o*3;
                f1out[(n*8 + o)*3 + c] = m * gsm[p*8 + o];
            }
        }
    }
}

// ---------------- final reduce ----------------
__global__ void reduce_kernel(float* __restrict__ out) {
    __shared__ float red[256];
    int j = blockIdx.x;
    float s = 0.f;
    for (int n = threadIdx.x; n < NN; n += 256) s += g_f0a[n*32 + j];
    red[threadIdx.x] = s;
    __syncthreads();
    for (int w = 128; w > 0; w >>= 1) {
        if (threadIdx.x < w) red[threadIdx.x] += red[threadIdx.x + w];
        __syncthreads();
    }
    if (threadIdx.x == 0) out[j] = red[0] * (1.0f/NN);
}

// ---------------- host ----------------
extern "C" void kernel_launch(void* const* d_in, const int* in_sizes, int n_in,
                              void* d_out, int out_size) {
    const float* radii   = (const float*)d_in[0];
    const int*   nbr     = (const int*)d_in[1];
    const int*   charges = (const int*)d_in[2];

    void* p;
    cudaGetSymbolAddress(&p, g_basis); float* basis = (float*)p;
    cudaGetSymbolAddress(&p, g_h2A);   float* h2A   = (float*)p;
    cudaGetSymbolAddress(&p, g_w1tA);  float* w1tA  = (float*)p;
    cudaGetSymbolAddress(&p, g_w2tA);  float* w2tA  = (float*)p;
    cudaGetSymbolAddress(&p, g_w3rA);  float* w3rA  = (float*)p;

    const int fm_smem = FM_SMEM_FLOATS * 4;   // 192256
    cudaFuncSetAttribute(fused_mlp, cudaFuncAttributeMaxDynamicSharedMemorySize, fm_smem);

    // smem (floats): NBUF*1600 + NBUF*16F + NPC*100F + KG*NSLOT*NPC + 8*NPC
    const int ns1 = (2*1600 + 2*16*4   + 8*100*4   + 5*48*8  + 64) * 4;   // pipelined, 34 KB
    const int ns2 = (1*1600 + 1*16*120 + 2*100*120 + 10*48*2 + 16) * 4;   // single-buf, 114.0 KB -> 2 CTA/SM
    const int ns3 = (2*1600 + 2*16*24  + 8*100*24  + 8*32*8  + 64) * 4;   // pipelined, 101.1 KB -> 2 CTA/SM
    cudaFuncSetAttribute((const void*)node_tp<1,8,256,true >, cudaFuncAttributeMaxDynamicSharedMemorySize, ns1);
    cudaFuncSetAttribute((const void*)node_tp<2,2,512,false>, cudaFuncAttributeMaxDynamicSharedMemorySize, ns2);
    cudaFuncSetAttribute((const void*)node_tp<3,8,256,true >, cudaFuncAttributeMaxDynamicSharedMemorySize, ns3);

    prep_kernel<<<(EE+255)/256, 256>>>(radii);

    prep_weights<<<(198000+255)/256, 256>>>(
        (const float*)d_in[3],  (const float*)d_in[5],  (const float*)d_in[7],
        (const float*)d_in[8],  (const float*)d_in[10], (const float*)d_in[12],
        (const float*)d_in[13], (const float*)d_in[15], (const float*)d_in[17]);

    Bias3 b1 = {{ (const float*)d_in[4],  (const float*)d_in[9],  (const float*)d_in[14] }};
    Bias3 b2 = {{ (const float*)d_in[6],  (const float*)d_in[11], (const float*)d_in[16] }};

    dim3 gridF(1, EE/256, 3);
    fused_mlp<<<gridF, 512, fm_smem>>>(basis, w1tA, w2tA, b1, b2, h2A);

    node_tp<1,8,256,true ><<<NN/8, 256, ns1>>>(nbr, charges, h2A,                   w3rA);
    node_tp<2,2,512,false><<<NN/2, 512, ns2>>>(nbr, charges, h2A + (size_t)EE*HH,   w3rA + 83200);
    node_tp<3,8,256,true ><<<NN/8, 256, ns3>>>(nbr, charges, h2A + (size_t)2*EE*HH, w3rA + 2*83200);

    reduce_kernel<<<32, 256>>>((float*)d_out);
}

// round 16
// speedup vs baseline: 1.1325x; 1.0509x over previous
#include <cuda_runtime.h>
#include <math.h>
#include <stdint.h>

#define NN 10000
#define KK 16
#define EE (NN*KK)
#define HH 100
#define NB 10
#define NBP 16

// ---------------- scratch ----------------
__device__ float g_basis[EE*NBP];
__device__ float g_u[EE*3];
__device__ float g_h2A[3*EE*HH];
__device__ float g_f0a[NN*32];
__device__ float g_f0b[NN*32];
__device__ float g_f1a[NN*24];
__device__ float g_f1b[NN*24];
__device__ float g_w1tA[3*NBP*HH];
__device__ float g_w2tA[3*HH*HH];
__device__ float g_w3rA[3*83200];

struct Bias3 { const float* b[3]; };

// ---------------- helpers ----------------
__device__ __forceinline__ float f2tf32f(float v) {
    uint32_t r;
    asm("cvt.rna.tf32.f32 %0, %1;" : "=r"(r) : "f"(v));
    return __uint_as_float(r);
}

__device__ __forceinline__ void mma_tf32(float* c, const uint32_t* a, const uint32_t* b) {
    asm volatile("mma.sync.aligned.m16n8k8.row.col.f32.tf32.tf32.f32 "
        "{%0,%1,%2,%3}, {%4,%5,%6,%7}, {%8,%9}, {%0,%1,%2,%3};"
        : "+f"(c[0]), "+f"(c[1]), "+f"(c[2]), "+f"(c[3])
        : "r"(a[0]), "r"(a[1]), "r"(a[2]), "r"(a[3]), "r"(b[0]), "r"(b[1]));
}

__device__ __forceinline__ void cp16(void* dst_smem, const void* src, int bytes) {
    uint32_t d = (uint32_t)__cvta_generic_to_shared(dst_smem);
    asm volatile("cp.async.cg.shared.global [%0], [%1], 16, %2;"
                 :: "r"(d), "l"(src), "r"(bytes));
}

// ---------------- prep ----------------
__global__ void prep_kernel(const float* __restrict__ radii) {
    int e = blockIdx.x*blockDim.x + threadIdx.x;
    if (e >= EE) return;
    float x = radii[e*3+0], y = radii[e*3+1], z = radii[e*3+2];
    float r = sqrtf(x*x + y*y + z*z);
    float inv = 1.0f / (r + 1e-8f);
    g_u[e*3+0] = x*inv; g_u[e*3+1] = y*inv; g_u[e*3+2] = z*inv;
    float rs = r * 1.8f;
    #pragma unroll
    for (int b = 0; b < NBP; b++) {
        float v = 0.f;
        if (b < NB) {
            float d = rs - (float)b;
            if (fabsf(d) < 1.0f) {
                float c = cospif(0.5f * d);
                v = f2tf32f(c * c);
            }
        }
        g_basis[e*NBP + b] = v;
    }
}

// ---------------- fused weight prep ----------------
__global__ void prep_weights(
    const float* __restrict__ w1a, const float* __restrict__ w2a, const float* __restrict__ w3a,
    const float* __restrict__ w1b, const float* __restrict__ w2b, const float* __restrict__ w3b,
    const float* __restrict__ w1c, const float* __restrict__ w2c, const float* __restrict__ w3c) {
    int i = blockIdx.x*blockDim.x + threadIdx.x;
    if (i < 4800) {
        int l = i / 1600, r = i - l*1600;
        int row = r / HH;
        const float* s = (l==0) ? w1a : (l==1) ? w1b : w1c;
        g_w1tA[i] = (row < NB) ? f2tf32f(s[r]) : 0.f;
    } else if (i < 34800) {
        int j = i - 4800;
        int l = j / 10000, r = j - l*10000;
        const float* s = (l==0) ? w2a : (l==1) ? w2b : w2c;
        g_w2tA[j] = f2tf32f(s[r]);
    } else {
        int j = i - 34800;
        if (j < 3200) {
            g_w3rA[j] = w3a[j];
        } else if (j < 3200 + 83200) {
            int r = j - 3200;
            int k = r / 832, d = r - k*832;
            int src;
            if      (d < 384) { int o=d%24,      i2=d/24;       src = o*16 + i2; }
            else if (d < 576) { int t=d-384; int o=t%24, i2=t/24; src = 384 + o*8 + i2; }
            else if (d < 704) { int t=d-576; int o=t%8,  i2=t/8;  src = 576 + o*16 + i2; }
            else if (d < 768) { int t=d-704; int o=t%8,  i2=t/8;  src = 704 + o*8 + i2; }
            else              { int t=d-768; int o=t%8,  i2=t/8;  src = 768 + o*8 + i2; }
            g_w3rA[83200 + r] = w3b[k*832 + src];
        } else if (j < 3200 + 83200 + 76800) {
            int r = j - 3200 - 83200;
            int k = r / 768, d = r - k*768;
            int src;
            if (d < 512) { int o=d%32, i2=d/32; src = o*16 + i2; }
            else         { int t=d-512; int o=t%32, i2=t/32; src = 512 + o*8 + i2; }
            g_w3rA[2*83200 + r] = w3c[k*768 + src];
        }
    }
}

// ---------------- fused radial MLP (R12/R15-verified) ----------------
#define FAS_S 20
#define FB1_S 136
#define FHS_S 104
#define FB2_S 136
#define FM_SMEM_FLOATS (256*FAS_S + 16*FB1_S + 256*FHS_S + 104*FB2_S)

__global__ void __launch_bounds__(512, 1)
fused_mlp(const float* __restrict__ basis,
          const float* __restrict__ w1A, const float* __restrict__ w2A,
          Bias3 b1, Bias3 b2,
          float* __restrict__ h2A) {
    extern __shared__ float smem[];
    float* As  = smem;
    float* Bs1 = As + 256*FAS_S;
    float* Hs  = Bs1 + 16*FB1_S;
    float* Bs2 = Hs + 256*FHS_S;

    const int z = blockIdx.z;
    const float* w1 = w1A + z*NBP*HH;
    const float* w2 = w2A + z*HH*HH;
    const float* bias1 = b1.b[z];
    const float* bias2 = b2.b[z];
    float* C = h2A + (size_t)z*EE*HH;

    const int tid = threadIdx.x;
    const int lane = tid & 31, wid = tid >> 5;
    const int wm = (wid & 3) * 64;
    const int wn = (wid >> 2) * 32;
    const int m0 = blockIdx.y * 256;
    const int gr = lane >> 2, tg = lane & 3;

    #pragma unroll
    for (int j = 0; j < 2; j++) {
        int c = tid + j*512;
        int row = c >> 2, kch = (c & 3) * 4;
        cp16(As + row*FAS_S + kch, basis + (size_t)(m0+row)*NBP + kch, 16);
    }
    {
        int k = tid >> 5, nch = (tid & 31) * 4;
        int bytes = (HH - nch) * 4;
        bytes = bytes < 0 ? 0 : (bytes > 16 ? 16 : bytes);
        const float* src = bytes ? (w1 + k*HH + nch) : w1;
        cp16(Bs1 + k*FB1_S + nch, src, bytes);
    }
    #pragma unroll
    for (int j = 0; j < 7; j++) {
        int c = tid + j*512;
        if (c < 3328) {
            int k = c >> 5, nch = (c & 31) * 4;
            int bytes = 0;
            if (k < HH) {
                bytes = (HH - nch) * 4;
                bytes = bytes < 0 ? 0 : (bytes > 16 ? 16 : bytes);
            }
            const float* src = bytes ? (w2 + k*HH + nch) : w2;
            cp16(Bs2 + k*FB2_S + nch, src, bytes);
        }
    }
    asm volatile("cp.async.commit_group;");
    for (int r = tid; r < 256; r += 512) {
        Hs[r*FHS_S + 100] = 0.f; Hs[r*FHS_S + 101] = 0.f;
        Hs[r*FHS_S + 102] = 0.f; Hs[r*FHS_S + 103] = 0.f;
    }
    asm volatile("cp.async.wait_group 0;");
    __syncthreads();

    float acc[4][4][4] = {};

    #pragma unroll
    for (int k8 = 0; k8 < 2; k8++) {
        int k0 = k8 * 8;
        uint32_t a[4][4], b[4][2];
        #pragma unroll
        for (int t2 = 0; t2 < 4; t2++) {
            int row = wm + t2*16 + gr;
            a[t2][0] = __float_as_uint(As[row*FAS_S     + k0 + tg]);
            a[t2][1] = __float_as_uint(As[(row+8)*FAS_S + k0 + tg]);
            a[t2][2] = __float_as_uint(As[row*FAS_S     + k0 + 4 + tg]);
            a[t2][3] = __float_as_uint(As[(row+8)*FAS_S + k0 + 4 + tg]);
        }
        #pragma unroll
        for (int j = 0; j < 4; j++) {
            int col = wn + j*8 + gr;
            b[j][0] = __float_as_uint(Bs1[(k0 + tg)*FB1_S     + col]);
            b[j][1] = __float_as_uint(Bs1[(k0 + 4 + tg)*FB1_S + col]);
        }
        #pragma unroll
        for (int t2 = 0; t2 < 4; t2++)
            #pragma unroll
            for (int j = 0; j < 4; j++)
                mma_tf32(acc[t2][j], a[t2], b[j]);
    }

    #pragma unroll
    for (int t2 = 0; t2 < 4; t2++) {
        #pragma unroll
        for (int j = 0; j < 4; j++) {
            #pragma unroll
            for (int h = 0; h < 2; h++) {
                int row = wm + t2*16 + gr + h*8;
                #pragma unroll
                for (int q = 0; q < 2; q++) {
                    int cn = wn + j*8 + tg*2 + q;
                    if (cn < HH) {
                        float v = fmaxf(acc[t2][j][h*2 + q] + bias1[cn], 0.f);
                        Hs[row*FHS_S + cn] = f2tf32f(v);
                    }
                }
            }
            #pragma unroll
            for (int q = 0; q < 4; q++) acc[t2][j][q] = 0.f;
        }
    }
    __syncthreads();

    #pragma unroll
    for (int k8 = 0; k8 < 13; k8++) {
        int k0 = k8 * 8;
        uint32_t a[4][4], b[4][2];
        #pragma unroll
        for (int t2 = 0; t2 < 4; t2++) {
            int row = wm + t2*16 + gr;
            a[t2][0] = __float_as_uint(Hs[row*FHS_S     + k0 + tg]);
            a[t2][1] = __float_as_uint(Hs[(row+8)*FHS_S + k0 + tg]);
            a[t2][2] = __float_as_uint(Hs[row*FHS_S     + k0 + 4 + tg]);
            a[t2][3] = __float_as_uint(Hs[(row+8)*FHS_S + k0 + 4 + tg]);
        }
        #pragma unroll
        for (int j = 0; j < 4; j++) {
            int col = wn + j*8 + gr;
            b[j][0] = __float_as_uint(Bs2[(k0 + tg)*FB2_S     + col]);
            b[j][1] = __float_as_uint(Bs2[(k0 + 4 + tg)*FB2_S + col]);
        }
        #pragma unroll
        for (int t2 = 0; t2 < 4; t2++)
            #pragma unroll
            for (int j = 0; j < 4; j++)
                mma_tf32(acc[t2][j], a[t2], b[j]);
    }

    #pragma unroll
    for (int t2 = 0; t2 < 4; t2++) {
        #pragma unroll
        for (int j = 0; j < 4; j++) {
            #pragma unroll
            for (int h = 0; h < 2; h++) {
                int row = m0 + wm + t2*16 + gr + h*8;
                #pragma unroll
                for (int q = 0; q < 2; q++) {
                    int cn = wn + j*8 + tg*2 + q;
                    if (cn < HH)
                        C[(size_t)row*HH + cn] = fmaxf(acc[t2][j][h*2 + q] + bias2[cn], 0.f);
                }
            }
        }
    }
}

// ---------------- node_tp for layers 1 & 3 (R15 pipelined, verbatim) ----------------
template<int LAYER, int NPC, int THREADS>
__global__ void __launch_bounds__(THREADS)
node_tp(const int* __restrict__ nbr, const int* __restrict__ charges,
        const float* __restrict__ h2, const float* __restrict__ w3r) {
    constexpr int F     = (LAYER==1) ? 4 : 24;
    constexpr int WTOT  = (LAYER==1) ? 32 : 768;
    constexpr int NSLOT = (LAYER==3) ? 32 : 48;
    constexpr int KG    = (THREADS / NSLOT) > 10 ? 10 : (THREADS / NSLOT);
    constexpr int MF    = HH * F;
    constexpr int FT    = (LAYER==3) ? 8 : 4;
    constexpr int NFG   = F / FT;
    constexpr int NCT   = 50 * NFG;

    extern __shared__ float sm[];
    float* h2s  = sm;                        // 2 x 1600
    float* zsA  = h2s + 2*16*HH;             // 2 x 16*F
    float* Ms   = zsA + 2*16*F;              // NPC*MF
    float* part = Ms + NPC*MF;               // KG*NSLOT*NPC
    float* gsm  = part + KG*NSLOT*NPC;       // NPC*8

    const int tid = threadIdx.x;
    const int nbase = blockIdx.x * NPC;

    const float* __restrict__ f0in = g_f0b;
    const float* __restrict__ f1in = g_f1b;
    float* f0out = g_f0a;
    float* f1out = g_f1a;

    auto stage_h2_async = [&](int p, int buf) {
        float* dst = h2s + buf*1600;
        const float* src = h2 + (size_t)(nbase+p)*KK*HH;
        for (int i = tid; i < 400; i += THREADS)
            cp16(dst + i*4, src + i*4, 16);
        asm volatile("cp.async.commit_group;");
    };
    auto gather_z = [&](int p, int buf) {
        float* zb = zsA + buf*(16*F);
        if (tid < 256) {
            int e = tid >> 4, j = tid & 15;
            int ge = (nbase+p)*KK + e;
            int idx = nbr[ge];
            float u0 = g_u[ge*3+0], u1 = g_u[ge*3+1], u2 = g_u[ge*3+2];
            if (LAYER == 1) {
                if (j == 0) {
                    float g0 = 0.5f * ((float)charges[idx] / 94.0f - 0.5f);
                    zb[e*F+0] = g0;
                    zb[e*F+1] = g0*u0; zb[e*F+2] = g0*u1; zb[e*F+3] = g0*u2;
                }
            } else {
                float g0j = 0.5f * f0in[idx*16 + j];
                zb[e*F + j] = g0j;
                if (j < 8) {
                    float a = 0.5f * f1in[idx*24 + j*3 + 0];
                    float b = 0.5f * f1in[idx*24 + j*3 + 1];
                    float c = 0.5f * f1in[idx*24 + j*3 + 2];
                    zb[e*F + 16 + j] = a*u0 + b*u1 + c*u2;
                }
            }
        }
    };
    auto phase_c = [&](int p, int buf) {
        const float* hb = h2s + buf*1600;
        const float* zb = zsA + buf*(16*F);
        float* Mp = Ms + p*MF;
        if (tid < NCT) {
            int kg = tid / NFG, fg = tid - kg*NFG;
            int k0 = kg*2, f0 = fg*FT;
            float accm0[FT] = {}, accm1[FT] = {};
            #pragma unroll 4
            for (int e = 0; e < 16; e++) {
                float2 hv = *(const float2*)&hb[e*HH + k0];
                float zv[FT];
                #pragma unroll
                for (int q = 0; q < FT; q += 4) {
                    float4 z4 = *(const float4*)&zb[e*F + f0 + q];
                    zv[q]=z4.x; zv[q+1]=z4.y; zv[q+2]=z4.z; zv[q+3]=z4.w;
                }
                #pragma unroll
                for (int ff = 0; ff < FT; ff++) {
                    accm0[ff] += hv.x * zv[ff];
                    accm1[ff] += hv.y * zv[ff];
                }
            }
            #pragma unroll
            for (int q = 0; q < FT; q += 4) {
                *(float4*)&Mp[k0*F + f0 + q]     = make_float4(accm0[q],accm0[q+1],accm0[q+2],accm0[q+3]);
                *(float4*)&Mp[(k0+1)*F + f0 + q] = make_float4(accm1[q],accm1[q+1],accm1[q+2],accm1[q+3]);
            }
        }
    };

    stage_h2_async(0, 0);
    gather_z(0, 0);
    for (int p = 0; p < NPC; p++) {
        int buf = p & 1;
        if (p + 1 < NPC) {
            stage_h2_async(p + 1, buf ^ 1);
            gather_z(p + 1, buf ^ 1);
            asm volatile("cp.async.wait_group 1;");
        } else {
            asm volatile("cp.async.wait_group 0;");
        }
        __syncthreads();
        phase_c(p, buf);
        __syncthreads();
    }

    if (tid < KG*NSLOT) {
        int s = tid % NSLOT, g = tid / NSLOT;
        float acc[NPC];
        #pragma unroll
        for (int p = 0; p < NPC; p++) acc[p] = 0.f;

        for (int k = g; k < HH; k += KG) {
            const float* wr = w3r + k*WTOT;
            if (LAYER == 1) {
                if (s < 24) {
                    float wv = wr[s];
                    #pragma unroll
                    for (int p = 0; p < NPC; p++) acc[p] += wv * Ms[p*MF + k*F + 0];
                } else {
                    int q = s - 24, o = q/3, c = q - o*3;
                    float wv = wr[24 + o];
                    #pragma unroll
                    for (int p = 0; p < NPC; p++) acc[p] += wv * Ms[p*MF + k*F + 1 + c];
                }
            } else {
                float w0[16], w1_[8];
                #pragma unroll
                for (int i = 0; i < 16; i++) w0[i] = wr[i*32 + s];
                #pragma unroll
                for (int i = 0; i < 8; i++)  w1_[i] = wr[512 + i*32 + s];
                #pragma unroll
                for (int p = 0; p < NPC; p++) {
                    const float* Mk = Ms + p*MF + k*F;
                    float4 a0=*(const float4*)(Mk),    a1=*(const float4*)(Mk+4);
                    float4 a2=*(const float4*)(Mk+8),  a3=*(const float4*)(Mk+12);
                    float4 b0=*(const float4*)(Mk+16), b1=*(const float4*)(Mk+20);
                    acc[p]+=w0[0]*a0.x;  acc[p]+=w0[1]*a0.y;  acc[p]+=w0[2]*a0.z;  acc[p]+=w0[3]*a0.w;
                    acc[p]+=w0[4]*a1.x;  acc[p]+=w0[5]*a1.y;  acc[p]+=w0[6]*a1.z;  acc[p]+=w0[7]*a1.w;
                    acc[p]+=w0[8]*a2.x;  acc[p]+=w0[9]*a2.y;  acc[p]+=w0[10]*a2.z; acc[p]+=w0[11]*a2.w;
                    acc[p]+=w0[12]*a3.x; acc[p]+=w0[13]*a3.y; acc[p]+=w0[14]*a3.z; acc[p]+=w0[15]*a3.w;
                    acc[p]+=w1_[0]*b0.x; acc[p]+=w1_[1]*b0.y; acc[p]+=w1_[2]*b0.z; acc[p]+=w1_[3]*b0.w;
                    acc[p]+=w1_[4]*b1.x; acc[p]+=w1_[5]*b1.y; acc[p]+=w1_[6]*b1.z; acc[p]+=w1_[7]*b1.w;
                }
            }
        }
        #pragma unroll
        for (int p = 0; p < NPC; p++)
            part[tid*NPC + p] = acc[p];
    }
    __syncthreads();

    for (int t2 = tid; t2 < NPC*NSLOT; t2 += THREADS) {
        int p = t2 / NSLOT, s = t2 % NSLOT;
        float m = 0.f;
        #pragma unroll
        for (int g = 0; g < KG; g++) m += part[(g*NSLOT + s)*NPC + p];
        m *= (1.0f/16.0f);
        int n = nbase + p;
        if (LAYER == 3) {
            f0out[n*32 + s] = fmaxf(m, 0.f);
        } else {
            part[s*NPC + p] = m;
            if (s >= 16 && s < 24)
                gsm[p*8 + (s-16)] = 1.0f / (1.0f + expf(-m));
        }
    }
    if (LAYER != 3) {
        __syncthreads();
        for (int t2 = tid; t2 < NPC*NSLOT; t2 += THREADS) {
            int p = t2 / NSLOT, s = t2 % NSLOT;
            int n = nbase + p;
            float m = part[s*NPC + p];
            if (s < 16) {
                f0out[n*16 + s] = fmaxf(m, 0.f);
            } else if (s >= 24) {
                int q = s - 24, o = q/3, c = q - o*3;
                f1out[(n*8 + o)*3 + c] = m * gsm[p*8 + o];
            }
        }
    }
}

// NOTE: layer-1/3 kernels write f0a/f1a; layer-2 reads f0a/f1a writes f0b/f1b.
// (Matches prior rounds' g_f0b-as-layer1-out convention via template dispatch below.)

// ---------------- layer-2 node kernel: k-chunked Phase C/D fusion, NPC=4 ----------------
// smem: h2sA 4*1600 | zsA 4*1920 | Mc 4*20*120 | part 10*48*4 | gsm 32  = 102528 B
#define L2KC 20
#define L2SMEM_FLOATS (4*1600 + 4*1920 + 4*L2KC*120 + 10*48*4 + 32)

__global__ void __launch_bounds__(512)
node_tp2(const int* __restrict__ nbr,
         const float* __restrict__ h2, const float* __restrict__ w3r) {
    constexpr int F = 120, WTOT = 832, NSLOT = 48, KG = 10, NPC = 4;

    extern __shared__ float sm[];
    float* h2sA = sm;                        // 4 x 1600
    float* zsA  = h2sA + 4*1600;             // 4 x 1920
    float* Mc   = zsA + 4*1920;              // 4 x 20 x 120
    float* part = Mc + 4*L2KC*120;           // 10*48*4
    float* gsm  = part + 10*48*4;            // 32

    const int tid = threadIdx.x;
    const int nbase = blockIdx.x * NPC;

    const float* __restrict__ f0in = g_f0a;
    const float* __restrict__ f1in = g_f1a;
    float* f0out = g_f0b;
    float* f1out = g_f1b;

    // stage h2 for 4 contiguous nodes (6400 floats contiguous in global)
    {
        const float* src = h2 + (size_t)nbase*KK*HH;
        for (int i = tid; i < 1600; i += 512)
            cp16(h2sA + i*4, src + i*4, 16);
        asm volatile("cp.async.commit_group;");
    }
    // gather z for 4 nodes
    for (int p = 0; p < NPC; p++) {
        float* zb = zsA + p*1920;
        if (tid < 256) {
            int e = tid >> 4, j = tid & 15;
            int ge = (nbase+p)*KK + e;
            int idx = nbr[ge];
            float u0 = g_u[ge*3+0], u1 = g_u[ge*3+1], u2 = g_u[ge*3+2];
            float g0j = 0.5f * f0in[idx*16 + j];
            zb[e*F + j] = g0j;
            zb[e*F + 24 + 0*32 + j] = g0j*u0;
            zb[e*F + 24 + 1*32 + j] = g0j*u1;
            zb[e*F + 24 + 2*32 + j] = g0j*u2;
            if (j < 8) {
                float a = 0.5f * f1in[idx*24 + j*3 + 0];
                float b = 0.5f * f1in[idx*24 + j*3 + 1];
                float c = 0.5f * f1in[idx*24 + j*3 + 2];
                zb[e*F + 16 + j] = a*u0 + b*u1 + c*u2;
                zb[e*F + 24 + 0*32 + 16 + j] = a;
                zb[e*F + 24 + 1*32 + 16 + j] = b;
                zb[e*F + 24 + 2*32 + 16 + j] = c;
                zb[e*F + 24 + 0*32 + 24 + j] = b*u2 - c*u1;
                zb[e*F + 24 + 1*32 + 24 + j] = c*u0 - a*u2;
                zb[e*F + 24 + 2*32 + 24 + j] = a*u1 - b*u0;
            }
        }
    }
    asm volatile("cp.async.wait_group 0;");
    __syncthreads();

    // Phase D accumulators held across k-chunks
    const int s = tid % NSLOT, g = tid / NSLOT;     // g < 10 for tid < 480
    float acc[NPC] = {0.f, 0.f, 0.f, 0.f};

    for (int cb = 0; cb < HH; cb += L2KC) {
        // ---- Phase C for this chunk: 400 threads (4 nodes x 10 ktiles x 10 fgroups) ----
        if (tid < 400) {
            int p = tid / 100, r = tid - p*100;
            int kg = r / 10, fg = r - kg*10;
            int k0 = cb + kg*2, f0 = fg*12;
            const float* hb = h2sA + p*1600;
            const float* zb = zsA + p*1920;
            float* Mp = Mc + p*(L2KC*120);
            float accm0[12] = {}, accm1[12] = {};
            #pragma unroll 4
            for (int e = 0; e < 16; e++) {
                float2 hv = *(const float2*)&hb[e*HH + k0];
                float zv[12];
                #pragma unroll
                for (int q = 0; q < 12; q += 4) {
                    float4 z4 = *(const float4*)&zb[e*F + f0 + q];
                    zv[q]=z4.x; zv[q+1]=z4.y; zv[q+2]=z4.z; zv[q+3]=z4.w;
                }
                #pragma unroll
                for (int ff = 0; ff < 12; ff++) {
                    accm0[ff] += hv.x * zv[ff];
                    accm1[ff] += hv.y * zv[ff];
                }
            }
            int kc = k0 - cb;
            #pragma unroll
            for (int q = 0; q < 12; q += 4) {
                *(float4*)&Mp[kc*120 + f0 + q]     = make_float4(accm0[q],accm0[q+1],accm0[q+2],accm0[q+3]);
                *(float4*)&Mp[(kc+1)*120 + f0 + q] = make_float4(accm1[q],accm1[q+1],accm1[q+2],accm1[q+3]);
            }
        }
        __syncthreads();

        // ---- Phase D for this chunk: 480 threads, k = cb+g, cb+g+10 (ascending) ----
        if (tid < KG*NSLOT) {
            #pragma unroll
            for (int half = 0; half < 2; half++) {
                int kk = g + half*10;               // chunk-local k
                int k = cb + kk;
                const float* wr = w3r + k*WTOT;
                if (s < 24) {
                    float w0[16], w1_[8];
                    #pragma unroll
                    for (int i = 0; i < 16; i++) w0[i] = wr[i*24 + s];
                    #pragma unroll
                    for (int i = 0; i < 8; i++)  w1_[i] = wr[384 + i*24 + s];
                    #pragma unroll
                    for (int p = 0; p < NPC; p++) {
                        const float* Mk = Mc + p*(L2KC*120) + kk*120;
                        float4 a0=*(const float4*)(Mk),    a1=*(const float4*)(Mk+4);
                        float4 a2=*(const float4*)(Mk+8),  a3=*(const float4*)(Mk+12);
                        float4 b0=*(const float4*)(Mk+16), b1=*(const float4*)(Mk+20);
                        acc[p]+=w0[0]*a0.x;  acc[p]+=w0[1]*a0.y;  acc[p]+=w0[2]*a0.z;  acc[p]+=w0[3]*a0.w;
                        acc[p]+=w0[4]*a1.x;  acc[p]+=w0[5]*a1.y;  acc[p]+=w0[6]*a1.z;  acc[p]+=w0[7]*a1.w;
                        acc[p]+=w0[8]*a2.x;  acc[p]+=w0[9]*a2.y;  acc[p]+=w0[10]*a2.z; acc[p]+=w0[11]*a2.w;
                        acc[p]+=w0[12]*a3.x; acc[p]+=w0[13]*a3.y; acc[p]+=w0[14]*a3.z; acc[p]+=w0[15]*a3.w;
                        acc[p]+=w1_[0]*b0.x; acc[p]+=w1_[1]*b0.y; acc[p]+=w1_[2]*b0.z; acc[p]+=w1_[3]*b0.w;
                        acc[p]+=w1_[4]*b1.x; acc[p]+=w1_[5]*b1.y; acc[p]+=w1_[6]*b1.z; acc[p]+=w1_[7]*b1.w;
                    }
                } else {
                    int q = s - 24, o = q/3, c = q - o*3;
                    float wv0[16], wv1[8], wv2[8];
                    #pragma unroll
                    for (int i = 0; i < 16; i++) wv0[i] = wr[576 + i*8 + o];
                    #pragma unroll
                    for (int i = 0; i < 8; i++)  wv1[i] = wr[704 + i*8 + o];
                    #pragma unroll
                    for (int i = 0; i < 8; i++)  wv2[i] = wr[768 + i*8 + o];
                    #pragma unroll
                    for (int p = 0; p < NPC; p++) {
                        const float* Mk = Mc + p*(L2KC*120) + kk*120 + 24 + c*32;
                        float4 a0=*(const float4*)(Mk),    a1=*(const float4*)(Mk+4);
                        float4 a2=*(const float4*)(Mk+8),  a3=*(const float4*)(Mk+12);
                        float4 b0=*(const float4*)(Mk+16), b1=*(const float4*)(Mk+20);
                        float4 c0=*(const float4*)(Mk+24), c1=*(const float4*)(Mk+28);
                        acc[p]+=wv0[0]*a0.x;  acc[p]+=wv0[1]*a0.y;  acc[p]+=wv0[2]*a0.z;  acc[p]+=wv0[3]*a0.w;
                        acc[p]+=wv0[4]*a1.x;  acc[p]+=wv0[5]*a1.y;  acc[p]+=wv0[6]*a1.z;  acc[p]+=wv0[7]*a1.w;
                        acc[p]+=wv0[8]*a2.x;  acc[p]+=wv0[9]*a2.y;  acc[p]+=wv0[10]*a2.z; acc[p]+=wv0[11]*a2.w;
                        acc[p]+=wv0[12]*a3.x; acc[p]+=wv0[13]*a3.y; acc[p]+=wv0[14]*a3.z; acc[p]+=wv0[15]*a3.w;
                        acc[p]+=wv1[0]*b0.x;  acc[p]+=wv1[1]*b0.y;  acc[p]+=wv1[2]*b0.z;  acc[p]+=wv1[3]*b0.w;
                        acc[p]+=wv1[4]*b1.x;  acc[p]+=wv1[5]*b1.y;  acc[p]+=wv1[6]*b1.z;  acc[p]+=wv1[7]*b1.w;
                        acc[p]+=wv2[0]*c0.x;  acc[p]+=wv2[1]*c0.y;  acc[p]+=wv2[2]*c0.z;  acc[p]+=wv2[3]*c0.w;
                        acc[p]+=wv2[4]*c1.x;  acc[p]+=wv2[5]*c1.y;  acc[p]+=wv2[6]*c1.z;  acc[p]+=wv2[7]*c1.w;
                    }
                }
            }
        }
        __syncthreads();
    }

    if (tid < KG*NSLOT) {
        #pragma unroll
        for (int p = 0; p < NPC; p++)
            part[tid*NPC + p] = acc[p];
    }
    __syncthreads();

    // Phase E (KG=10 sum order identical to before)
    for (int t2 = tid; t2 < NPC*NSLOT; t2 += 512) {
        int p = t2 / NSLOT, s2 = t2 % NSLOT;
        float m = 0.f;
        #pragma unroll
        for (int g2 = 0; g2 < KG; g2++) m += part[(g2*NSLOT + s2)*NPC + p];
        m *= (1.0f/16.0f);
        part[s2*NPC + p] = m;
        if (s2 >= 16 && s2 < 24)
            gsm[p*8 + (s2-16)] = 1.0f / (1.0f + expf(-m));
    }
    __syncthreads();
    for (int t2 = tid; t2 < NPC*NSLOT; t2 += 512) {
        int p = t2 / NSLOT, s2 = t2 % NSLOT;
        int n = nbase + p;
        float m = part[s2*NPC + p];
        if (s2 < 16) {
            f0out[n*16 + s2] = fmaxf(m, 0.f);
        } else if (s2 >= 24) {
            int q = s2 - 24, o = q/3, c = q - o*3;
            f1out[(n*8 + o)*3 + c] = m * gsm[p*8 + o];
        }
    }
}

// ---------------- final reduce ----------------
__global__ void reduce_kernel(float* __restrict__ out) {
    __shared__ float red[256];
    int j = blockIdx.x;
    float s = 0.f;
    for (int n = threadIdx.x; n < NN; n += 256) s += g_f0a[n*32 + j];
    red[threadIdx.x] = s;
    __syncthreads();
    for (int w = 128; w > 0; w >>= 1) {
        if (threadIdx.x < w) red[threadIdx.x] += red[threadIdx.x + w];
        __syncthreads();
    }
    if (threadIdx.x == 0) out[j] = red[0] * (1.0f/NN);
}

// ---------------- host ----------------
extern "C" void kernel_launch(void* const* d_in, const int* in_sizes, int n_in,
                              void* d_out, int out_size) {
    const float* radii   = (const float*)d_in[0];
    const int*   nbr     = (const int*)d_in[1];
    const int*   charges = (const int*)d_in[2];

    void* p;
    cudaGetSymbolAddress(&p, g_basis); float* basis = (float*)p;
    cudaGetSymbolAddress(&p, g_h2A);   float* h2A   = (float*)p;
    cudaGetSymbolAddress(&p, g_w1tA);  float* w1tA  = (float*)p;
    cudaGetSymbolAddress(&p, g_w2tA);  float* w2tA  = (float*)p;
    cudaGetSymbolAddress(&p, g_w3rA);  float* w3rA  = (float*)p;

    const int fm_smem = FM_SMEM_FLOATS * 4;
    cudaFuncSetAttribute(fused_mlp, cudaFuncAttributeMaxDynamicSharedMemorySize, fm_smem);

    const int ns1 = (2*1600 + 2*16*4  + 8*100*4  + 5*48*8 + 64) * 4;
    const int ns3 = (2*1600 + 2*16*24 + 8*100*24 + 8*32*8 + 64) * 4;
    const int ns2 = L2SMEM_FLOATS * 4;    // 102528
    cudaFuncSetAttribute((const void*)node_tp<1,8,256>, cudaFuncAttributeMaxDynamicSharedMemorySize, ns1);
    cudaFuncSetAttribute((const void*)node_tp<3,8,256>, cudaFuncAttributeMaxDynamicSharedMemorySize, ns3);
    cudaFuncSetAttribute((const void*)node_tp2, cudaFuncAttributeMaxDynamicSharedMemorySize, ns2);

    prep_kernel<<<(EE+255)/256, 256>>>(radii);

    prep_weights<<<(198000+255)/256, 256>>>(
        (const float*)d_in[3],  (const float*)d_in[5],  (const float*)d_in[7],
        (const float*)d_in[8],  (const float*)d_in[10], (const float*)d_in[12],
        (const float*)d_in[13], (const float*)d_in[15], (const float*)d_in[17]);

    Bias3 b1 = {{ (const float*)d_in[4],  (const float*)d_in[9],  (const float*)d_in[14] }};
    Bias3 b2 = {{ (const float*)d_in[6],  (const float*)d_in[11], (const float*)d_in[16] }};

    dim3 gridF(1, EE/256, 3);
    fused_mlp<<<gridF, 512, fm_smem>>>(basis, w1tA, w2tA, b1, b2, h2A);

    // L1: reads charges, writes f0a/f1a (template uses f0out=g_f0a,f1out=g_f1a)
    node_tp<1,8,256><<<NN/8, 256, ns1>>>(nbr, charges, h2A, w3rA);
    // L2: reads f0a/f1a, writes f0b/f1b
    node_tp2<<<NN/4, 512, ns2>>>(nbr, h2A + (size_t)EE*HH, w3rA + 83200);
    // L3: reads f0b/f1b, writes f0a
    node_tp<3,8,256><<<NN/8, 256, ns3>>>(nbr, charges, h2A + (size_t)2*EE*HH, w3rA + 2*83200);

    reduce_kernel<<<32, 256>>>((float*)d_out);
}